// round 5
// baseline (speedup 1.0000x reference)
#include <cuda_runtime.h>
#include <math.h>

// Problem constants
#define BB 8
#define TT 4096
#define DD 256
#define MM (BB*TT)      // 32768 rows
#define KK 512          // 2*D

// GEMM tiling
#define BM 128
#define BN 128
#define BK 16
#define NTHREADS 256

typedef unsigned long long ull;

// Scratch (static device globals — allocation-free per harness rules)
__device__ float g_U[(size_t)MM * KK];   // 64 MB: u = x_cat @ Wm^T + bm
__device__ float g_S[(size_t)MM * KK];   // 64 MB: scanned state [re|im]

// ---------------- packed f32x2 helpers ----------------
__device__ __forceinline__ ull pack_dup(float x) {
    unsigned u = __float_as_uint(x);
    ull r;
    asm("mov.b64 %0, {%1, %1};" : "=l"(r) : "r"(u));
    return r;
}
__device__ __forceinline__ void fma2(ull& acc, ull a, ull b) {
    asm("fma.rn.f32x2 %0, %1, %2, %0;" : "+l"(acc) : "l"(a), "l"(b));
}
__device__ __forceinline__ float2 unpack2(ull v) {
    unsigned lo, hi;
    asm("mov.b64 {%0, %1}, %2;" : "=r"(lo), "=r"(hi) : "l"(v));
    return make_float2(__uint_as_float(lo), __uint_as_float(hi));
}

// ---------------- GEMM ----------------
// C[m,n] = sum_k A[m,k] * W[n,k] + bias[n]   (W row-major [n][k], k-stride 512)
//
// MODE 0: A = concat(x_re, x_im) along k (split at 256); W = Wm; C = g_U (ldc=512)
// MODE 1: A = g_S; W = Wo for n<512 else Wg; bias bo/bg; gate cols get
//         clip(sigmoid(.), 0.01, 0.99); C = out (ldc=768)
template <int MODE>
__global__ void __launch_bounds__(NTHREADS, 2)
gemm_kernel(const float* __restrict__ Are, const float* __restrict__ Aim,
            const float* __restrict__ W0, const float* __restrict__ W1,
            const float* __restrict__ bias0, const float* __restrict__ bias1,
            float* __restrict__ Cout, int ldc)
{
    __shared__ float As[2][BK][BM + 4];
    __shared__ float Bs[2][BK][BN + 4];

    const int tid = threadIdx.x;
    const int tm = tid >> 4;          // 0..15
    const int tn = tid & 15;          // 0..15
    const int lr = tid >> 2;          // loader row 0..63
    const int lc = tid & 3;           // loader col4 0..3
    const int m0 = blockIdx.y * BM;
    const int n0 = blockIdx.x * BN;

    const bool gate_blk = (MODE == 1) && (blockIdx.x >= 4);
    const float* __restrict__ Wsel = gate_blk ? W1 : W0;
    const int nW = gate_blk ? (n0 - 512) : n0;

    // ---- global fetch (into registers) ----
    float4 a0, a1, b0, b1;

    auto fetchA = [&](int k0) {
        const float* base;
        if (MODE == 0) {
            base = (k0 < 256) ? (Are + (size_t)m0 * DD + k0)
                              : (Aim + (size_t)m0 * DD + (k0 - 256));
            a0 = *(const float4*)(base + (size_t)lr * DD + lc * 4);
            a1 = *(const float4*)(base + (size_t)(lr + 64) * DD + lc * 4);
        } else {
            base = g_S + (size_t)m0 * KK + k0;
            a0 = *(const float4*)(base + (size_t)lr * KK + lc * 4);
            a1 = *(const float4*)(base + (size_t)(lr + 64) * KK + lc * 4);
        }
    };
    auto fetchB = [&](int k0) {
        const float* base = Wsel + (size_t)nW * KK + k0;
        b0 = *(const float4*)(base + (size_t)lr * KK + lc * 4);
        b1 = *(const float4*)(base + (size_t)(lr + 64) * KK + lc * 4);
    };
    auto store_smem = [&](int buf) {
        float av0[4] = {a0.x, a0.y, a0.z, a0.w};
        float av1[4] = {a1.x, a1.y, a1.z, a1.w};
        float bv0[4] = {b0.x, b0.y, b0.z, b0.w};
        float bv1[4] = {b1.x, b1.y, b1.z, b1.w};
#pragma unroll
        for (int j = 0; j < 4; j++) {
            As[buf][lc * 4 + j][lr]      = av0[j];
            As[buf][lc * 4 + j][lr + 64] = av1[j];
            Bs[buf][lc * 4 + j][lr]      = bv0[j];
            Bs[buf][lc * 4 + j][lr + 64] = bv1[j];
        }
    };

    // prologue
    fetchA(0); fetchB(0);
    store_smem(0);
    __syncthreads();

    ull acc[8][4];
#pragma unroll
    for (int i = 0; i < 8; i++)
#pragma unroll
        for (int p = 0; p < 4; p++) acc[i][p] = 0ull;

    const int NK = KK / BK;   // 32
#pragma unroll 1
    for (int kt = 0; kt < NK; kt++) {
        const int buf = kt & 1;
        const bool has_next = (kt + 1 < NK);
        if (has_next) { fetchA((kt + 1) * BK); fetchB((kt + 1) * BK); }

#pragma unroll
        for (int k = 0; k < BK; k++) {
            const float4 av0 = *(const float4*)&As[buf][k][tm * 8];
            const float4 av1 = *(const float4*)&As[buf][k][tm * 8 + 4];
            const ulonglong2 bv0 = *(const ulonglong2*)&Bs[buf][k][tn * 8];
            const ulonglong2 bv1 = *(const ulonglong2*)&Bs[buf][k][tn * 8 + 4];
            ull ap[8] = {pack_dup(av0.x), pack_dup(av0.y), pack_dup(av0.z), pack_dup(av0.w),
                         pack_dup(av1.x), pack_dup(av1.y), pack_dup(av1.z), pack_dup(av1.w)};
            ull bp[4] = {bv0.x, bv0.y, bv1.x, bv1.y};
#pragma unroll
            for (int i = 0; i < 8; i++)
#pragma unroll
                for (int p = 0; p < 4; p++)
                    fma2(acc[i][p], ap[i], bp[p]);
        }

        if (has_next) {
            store_smem(buf ^ 1);
            __syncthreads();
        }
    }

    // ---- epilogue ----
    const int ncol = n0 + tn * 8;
    float bias[8];
#pragma unroll
    for (int j = 0; j < 8; j++) {
        if (MODE == 0)       bias[j] = bias0[ncol + j];
        else if (gate_blk)   bias[j] = bias1[ncol - 512 + j];
        else                 bias[j] = bias0[ncol + j];
    }

    float* __restrict__ C = (MODE == 0) ? g_U : Cout;

#pragma unroll
    for (int i = 0; i < 8; i++) {
        const int m = m0 + tm * 8 + i;
        float v[8];
#pragma unroll
        for (int p = 0; p < 4; p++) {
            float2 f = unpack2(acc[i][p]);
            v[2 * p]     = f.x + bias[2 * p];
            v[2 * p + 1] = f.y + bias[2 * p + 1];
        }
        if (MODE == 1 && gate_blk) {
#pragma unroll
            for (int j = 0; j < 8; j++) {
                float s = 1.0f / (1.0f + expf(-v[j]));
                v[j] = fminf(fmaxf(s, 0.01f), 0.99f);
            }
        }
        float* c = C + (size_t)m * ldc + ncol;
        *(float4*)c       = make_float4(v[0], v[1], v[2], v[3]);
        *(float4*)(c + 4) = make_float4(v[4], v[5], v[6], v[7]);
    }
}

// ---------------- diagonal complex scan ----------------
// One thread per (b, d) channel: s_t = s_{t-1} * decay + u_t
__global__ void scan_kernel(const float* __restrict__ s0_re,
                            const float* __restrict__ s0_im,
                            const float* __restrict__ decay_re,
                            const float* __restrict__ decay_im)
{
    const int id = blockIdx.x * blockDim.x + threadIdx.x;   // 0..2047
    const int b = id >> 8;
    const int d = id & 255;

    const float dr = 1.0f / (1.0f + expf(-decay_re[d]));
    const float di = decay_im[d];
    float sr = s0_re[id];
    float si = s0_im[id];

    const float* __restrict__ U = g_U + (size_t)b * TT * KK + d;
    float*       __restrict__ S = g_S + (size_t)b * TT * KK + d;

#pragma unroll 8
    for (int t = 0; t < TT; t++) {
        const float ur = U[(size_t)t * KK];
        const float ui = U[(size_t)t * KK + 256];
        const float nr = fmaf(sr, dr, fmaf(-si, di, ur));
        const float ni = fmaf(sr, di, fmaf(si, dr, ui));
        sr = nr; si = ni;
        S[(size_t)t * KK]       = nr;
        S[(size_t)t * KK + 256] = ni;
    }
}

// ---------------- launch ----------------
extern "C" void kernel_launch(void* const* d_in, const int* in_sizes, int n_in,
                              void* d_out, int out_size)
{
    (void)in_sizes; (void)n_in; (void)out_size;
    const float* x_re     = (const float*)d_in[0];
    const float* x_im     = (const float*)d_in[1];
    const float* s0_re    = (const float*)d_in[2];
    const float* s0_im    = (const float*)d_in[3];
    const float* decay_re = (const float*)d_in[4];
    const float* decay_im = (const float*)d_in[5];
    const float* Wm       = (const float*)d_in[6];
    const float* bm       = (const float*)d_in[7];
    const float* Wo       = (const float*)d_in[8];
    const float* bo       = (const float*)d_in[9];
    const float* Wg       = (const float*)d_in[10];
    const float* bg       = (const float*)d_in[11];
    float* out = (float*)d_out;

    // 1) u = x_cat @ Wm^T + bm  -> g_U
    gemm_kernel<0><<<dim3(KK / BN, MM / BM), NTHREADS>>>(
        x_re, x_im, Wm, nullptr, bm, nullptr, nullptr, KK);

    // 2) diagonal complex scan g_U -> g_S
    scan_kernel<<<16, 128>>>(s0_re, s0_im, decay_re, decay_im);

    // 3) [source | gate] = s_cat @ [Wo;Wg]^T + [bo;bg], gate = clip(sigmoid)
    gemm_kernel<1><<<dim3(768 / BN, MM / BM), NTHREADS>>>(
        nullptr, nullptr, Wo, Wg, bo, bg, out, 768);
}

// round 6
// speedup vs baseline: 2.7796x; 2.7796x over previous
#include <cuda_runtime.h>
#include <math.h>

// Problem constants
#define BB 8
#define TT 4096
#define DD 256
#define MM (BB*TT)      // 32768 rows
#define KK 512          // 2*D
#define NCH 2048        // B*D channels

// GEMM tiling
#define BM 128
#define BN 128
#define BK 16
#define NTHREADS 256

// Scan chunking
#define CHUNK 128
#define NCHUNK (TT/CHUNK)   // 32

typedef unsigned long long ull;

// Scratch (static device globals — allocation-free per harness rules)
__device__ float g_U[(size_t)MM * KK];   // 64 MB: u = x_cat @ Wm^T + bm
__device__ float g_S[(size_t)MM * KK];   // 64 MB: scanned state [re|im]
__device__ float g_E[2 * NCHUNK * NCH];  // chunk-end states (re plane | im plane)
__device__ float g_C[2 * NCHUNK * NCH];  // carry-in per chunk (re plane | im plane)

// ---------------- packed f32x2 helpers ----------------
__device__ __forceinline__ ull pack_dup(float x) {
    unsigned u = __float_as_uint(x);
    ull r;
    asm("mov.b64 %0, {%1, %1};" : "=l"(r) : "r"(u));
    return r;
}
__device__ __forceinline__ void fma2(ull& acc, ull a, ull b) {
    asm("fma.rn.f32x2 %0, %1, %2, %0;" : "+l"(acc) : "l"(a), "l"(b));
}
__device__ __forceinline__ float2 unpack2(ull v) {
    unsigned lo, hi;
    asm("mov.b64 {%0, %1}, %2;" : "=r"(lo), "=r"(hi) : "l"(v));
    return make_float2(__uint_as_float(lo), __uint_as_float(hi));
}

// ---------------- GEMM ----------------
// C[m,n] = sum_k A[m,k] * W[n,k] + bias[n]   (W row-major [n][k], k-stride 512)
//
// MODE 0: A = concat(x_re, x_im) along k (split at 256); W = Wm; C = g_U (ldc=512)
// MODE 1: A = g_S; W = Wo for n<512 else Wg; bias bo/bg; gate cols get
//         clip(sigmoid(.), 0.01, 0.99); C = out (ldc=768)
template <int MODE>
__global__ void __launch_bounds__(NTHREADS, 2)
gemm_kernel(const float* __restrict__ Are, const float* __restrict__ Aim,
            const float* __restrict__ W0, const float* __restrict__ W1,
            const float* __restrict__ bias0, const float* __restrict__ bias1,
            float* __restrict__ Cout, int ldc)
{
    __shared__ float As[2][BK][BM + 4];
    __shared__ float Bs[2][BK][BN + 4];

    const int tid = threadIdx.x;
    const int tm = tid >> 4;          // 0..15
    const int tn = tid & 15;          // 0..15
    const int lr = tid >> 2;          // loader row 0..63
    const int lc = tid & 3;           // loader col4 0..3
    const int m0 = blockIdx.y * BM;
    const int n0 = blockIdx.x * BN;

    const bool gate_blk = (MODE == 1) && (blockIdx.x >= 4);
    const float* __restrict__ Wsel = gate_blk ? W1 : W0;
    const int nW = gate_blk ? (n0 - 512) : n0;

    // ---- global fetch (into registers) ----
    float4 a0, a1, b0, b1;

    auto fetchA = [&](int k0) {
        const float* base;
        if (MODE == 0) {
            base = (k0 < 256) ? (Are + (size_t)m0 * DD + k0)
                              : (Aim + (size_t)m0 * DD + (k0 - 256));
            a0 = *(const float4*)(base + (size_t)lr * DD + lc * 4);
            a1 = *(const float4*)(base + (size_t)(lr + 64) * DD + lc * 4);
        } else {
            base = g_S + (size_t)m0 * KK + k0;
            a0 = *(const float4*)(base + (size_t)lr * KK + lc * 4);
            a1 = *(const float4*)(base + (size_t)(lr + 64) * KK + lc * 4);
        }
    };
    auto fetchB = [&](int k0) {
        const float* base = Wsel + (size_t)nW * KK + k0;
        b0 = *(const float4*)(base + (size_t)lr * KK + lc * 4);
        b1 = *(const float4*)(base + (size_t)(lr + 64) * KK + lc * 4);
    };
    auto store_smem = [&](int buf) {
        float av0[4] = {a0.x, a0.y, a0.z, a0.w};
        float av1[4] = {a1.x, a1.y, a1.z, a1.w};
        float bv0[4] = {b0.x, b0.y, b0.z, b0.w};
        float bv1[4] = {b1.x, b1.y, b1.z, b1.w};
#pragma unroll
        for (int j = 0; j < 4; j++) {
            As[buf][lc * 4 + j][lr]      = av0[j];
            As[buf][lc * 4 + j][lr + 64] = av1[j];
            Bs[buf][lc * 4 + j][lr]      = bv0[j];
            Bs[buf][lc * 4 + j][lr + 64] = bv1[j];
        }
    };

    // prologue
    fetchA(0); fetchB(0);
    store_smem(0);
    __syncthreads();

    ull acc[8][4];
#pragma unroll
    for (int i = 0; i < 8; i++)
#pragma unroll
        for (int p = 0; p < 4; p++) acc[i][p] = 0ull;

    const int NK = KK / BK;   // 32
#pragma unroll 1
    for (int kt = 0; kt < NK; kt++) {
        const int buf = kt & 1;
        const bool has_next = (kt + 1 < NK);
        if (has_next) { fetchA((kt + 1) * BK); fetchB((kt + 1) * BK); }

#pragma unroll
        for (int k = 0; k < BK; k++) {
            const float4 av0 = *(const float4*)&As[buf][k][tm * 8];
            const float4 av1 = *(const float4*)&As[buf][k][tm * 8 + 4];
            const ulonglong2 bv0 = *(const ulonglong2*)&Bs[buf][k][tn * 8];
            const ulonglong2 bv1 = *(const ulonglong2*)&Bs[buf][k][tn * 8 + 4];
            ull ap[8] = {pack_dup(av0.x), pack_dup(av0.y), pack_dup(av0.z), pack_dup(av0.w),
                         pack_dup(av1.x), pack_dup(av1.y), pack_dup(av1.z), pack_dup(av1.w)};
            ull bp[4] = {bv0.x, bv0.y, bv1.x, bv1.y};
#pragma unroll
            for (int i = 0; i < 8; i++)
#pragma unroll
                for (int p = 0; p < 4; p++)
                    fma2(acc[i][p], ap[i], bp[p]);
        }

        if (has_next) {
            store_smem(buf ^ 1);
            __syncthreads();
        }
    }

    // ---- epilogue ----
    const int ncol = n0 + tn * 8;
    float bias[8];
#pragma unroll
    for (int j = 0; j < 8; j++) {
        if (MODE == 0)       bias[j] = bias0[ncol + j];
        else if (gate_blk)   bias[j] = bias1[ncol - 512 + j];
        else                 bias[j] = bias0[ncol + j];
    }

    float* __restrict__ C = (MODE == 0) ? g_U : Cout;

#pragma unroll
    for (int i = 0; i < 8; i++) {
        const int m = m0 + tm * 8 + i;
        float v[8];
#pragma unroll
        for (int p = 0; p < 4; p++) {
            float2 f = unpack2(acc[i][p]);
            v[2 * p]     = f.x + bias[2 * p];
            v[2 * p + 1] = f.y + bias[2 * p + 1];
        }
        if (MODE == 1 && gate_blk) {
#pragma unroll
            for (int j = 0; j < 8; j++) {
                float s = 1.0f / (1.0f + expf(-v[j]));
                v[j] = fminf(fmaxf(s, 0.01f), 0.99f);
            }
        }
        float* c = C + (size_t)m * ldc + ncol;
        *(float4*)c       = make_float4(v[0], v[1], v[2], v[3]);
        *(float4*)(c + 4) = make_float4(v[4], v[5], v[6], v[7]);
    }
}

// ---------------- chunk-parallel diagonal complex scan ----------------
// Linear recurrence s_t = s_{t-1}*d + u_t with diagonal complex d splits into
// per-chunk local scans + a cheap sequential carry combine.

// Pass A: per (channel, chunk), scan chunk from zero state, emit chunk-end state.
__global__ void __launch_bounds__(256)
scan_passA(const float* __restrict__ decay_re, const float* __restrict__ decay_im)
{
    const int id = blockIdx.x * blockDim.x + threadIdx.x;  // 0..65535
    const int ch = id & (NCH - 1);        // channel = b*256 + d
    const int c  = id >> 11;              // chunk 0..31
    const int b = ch >> 8;
    const int d = ch & 255;

    const float dr = 1.0f / (1.0f + expf(-decay_re[d]));
    const float di = decay_im[d];

    const float* __restrict__ U = g_U + ((size_t)b * TT + (size_t)c * CHUNK) * KK + d;

    float sr = 0.0f, si = 0.0f;
#pragma unroll 4
    for (int j = 0; j < CHUNK; j++) {
        const float ur = __ldg(U + (size_t)j * KK);
        const float ui = __ldg(U + (size_t)j * KK + 256);
        const float nr = fmaf(sr, dr, fmaf(-si, di, ur));
        const float ni = fmaf(sr, di, fmaf(si, dr, ui));
        sr = nr; si = ni;
    }
    g_E[c * NCH + ch]                = sr;
    g_E[NCHUNK * NCH + c * NCH + ch] = si;
}

// Pass B: per channel, sequential combine of 32 chunk-end states.
// carry_{c+1} = carry_c * d^CHUNK + e_c ; store carry_c (state entering chunk c).
__global__ void __launch_bounds__(256)
scan_passB(const float* __restrict__ s0_re, const float* __restrict__ s0_im,
           const float* __restrict__ decay_re, const float* __restrict__ decay_im)
{
    const int id = blockIdx.x * blockDim.x + threadIdx.x;  // 0..2047
    const int d = id & 255;

    float dr = 1.0f / (1.0f + expf(-decay_re[d]));
    float di = decay_im[d];

    // d^CHUNK by repeated squaring (CHUNK = 2^7)
    float pr = dr, pi = di;
#pragma unroll
    for (int s = 0; s < 7; s++) {
        const float nr = pr * pr - pi * pi;
        const float ni = 2.0f * pr * pi;
        pr = nr; pi = ni;
    }

    float cr = s0_re[id];
    float ci = s0_im[id];
#pragma unroll
    for (int c = 0; c < NCHUNK; c++) {
        g_C[c * NCH + id]                = cr;
        g_C[NCHUNK * NCH + c * NCH + id] = ci;
        const float er = g_E[c * NCH + id];
        const float ei = g_E[NCHUNK * NCH + c * NCH + id];
        const float nr = fmaf(cr, pr, fmaf(-ci, pi, er));
        const float ni = fmaf(cr, pi, fmaf(ci, pr, ei));
        cr = nr; ci = ni;
    }
}

// Pass C: per (channel, chunk), re-scan seeded with the correct carry; write S.
__global__ void __launch_bounds__(256)
scan_passC(const float* __restrict__ decay_re, const float* __restrict__ decay_im)
{
    const int id = blockIdx.x * blockDim.x + threadIdx.x;  // 0..65535
    const int ch = id & (NCH - 1);
    const int c  = id >> 11;
    const int b = ch >> 8;
    const int d = ch & 255;

    const float dr = 1.0f / (1.0f + expf(-decay_re[d]));
    const float di = decay_im[d];

    const size_t off = ((size_t)b * TT + (size_t)c * CHUNK) * KK + d;
    const float* __restrict__ U = g_U + off;
    float*       __restrict__ S = g_S + off;

    float sr = g_C[c * NCH + ch];
    float si = g_C[NCHUNK * NCH + c * NCH + ch];

#pragma unroll 4
    for (int j = 0; j < CHUNK; j++) {
        const float ur = __ldg(U + (size_t)j * KK);
        const float ui = __ldg(U + (size_t)j * KK + 256);
        const float nr = fmaf(sr, dr, fmaf(-si, di, ur));
        const float ni = fmaf(sr, di, fmaf(si, dr, ui));
        sr = nr; si = ni;
        S[(size_t)j * KK]       = nr;
        S[(size_t)j * KK + 256] = ni;
    }
}

// ---------------- launch ----------------
extern "C" void kernel_launch(void* const* d_in, const int* in_sizes, int n_in,
                              void* d_out, int out_size)
{
    (void)in_sizes; (void)n_in; (void)out_size;
    const float* x_re     = (const float*)d_in[0];
    const float* x_im     = (const float*)d_in[1];
    const float* s0_re    = (const float*)d_in[2];
    const float* s0_im    = (const float*)d_in[3];
    const float* decay_re = (const float*)d_in[4];
    const float* decay_im = (const float*)d_in[5];
    const float* Wm       = (const float*)d_in[6];
    const float* bm       = (const float*)d_in[7];
    const float* Wo       = (const float*)d_in[8];
    const float* bo       = (const float*)d_in[9];
    const float* Wg       = (const float*)d_in[10];
    const float* bg       = (const float*)d_in[11];
    float* out = (float*)d_out;

    // 1) u = x_cat @ Wm^T + bm  -> g_U
    gemm_kernel<0><<<dim3(KK / BN, MM / BM), NTHREADS>>>(
        x_re, x_im, Wm, nullptr, bm, nullptr, nullptr, KK);

    // 2) chunk-parallel diagonal complex scan g_U -> g_S
    scan_passA<<<(NCH * NCHUNK) / 256, 256>>>(decay_re, decay_im);
    scan_passB<<<NCH / 256, 256>>>(s0_re, s0_im, decay_re, decay_im);
    scan_passC<<<(NCH * NCHUNK) / 256, 256>>>(decay_re, decay_im);

    // 3) [source | gate] = s_cat @ [Wo;Wg]^T + [bo;bg], gate = clip(sigmoid)
    gemm_kernel<1><<<dim3(768 / BN, MM / BM), NTHREADS>>>(
        nullptr, nullptr, Wo, Wg, bo, bg, out, 768);
}